// round 14
// baseline (speedup 1.0000x reference)
#include <cuda_runtime.h>
#include <cstdint>

// Fixed shapes per reference: B=256, L=512, N=50000
constexpr int B_SZ    = 256;
constexpr int L_SEQ   = 512;
constexpr int N_LOC   = 50000;
constexpr int HSIZE   = 1024;          // hash slots (pow2), load factor <= 0.5
constexpr int SEGS    = 8;             // column segments per row
constexpr int SEG_LEN = 6256;          // 8*6256 = 50048 >= 50000
constexpr int CAP     = 512;           // max distinct keys per (row,seg)
constexpr int NT      = 256;

// Global scratch (__device__ arrays only — no runtime alloc)
__device__ int   g_cnt[B_SZ * SEGS];
__device__ int   g_key[B_SZ * SEGS * CAP];
__device__ float g_val[B_SZ * SEGS * CAP];

// ---------------------------------------------------------------------------
// Primary: one CTA per row. Releases the dependent grid immediately, then
// builds the dedup hash and compacts (key,val) into per-(row,seg) buckets.
// ---------------------------------------------------------------------------
__global__ __launch_bounds__(NT, 4)
void build_kernel(const int* __restrict__ loc_seq,
                  const int* __restrict__ mask,
                  const float* __restrict__ rw_p,
                  const float* __restrict__ fw_p)
{
    // Release the dependent (fill) grid right away — its zeroing phase
    // depends on nothing we produce.
    asm volatile("griddepcontrol.launch_dependents;" ::: "memory");

    const int b   = blockIdx.x;
    const int tid = threadIdx.x;

    __shared__ int      h_key[HSIZE];
    __shared__ int      h_cnt[HSIZE];
    __shared__ unsigned h_rec[HSIZE];   // float bits; all values >= 0
    __shared__ int      s_maxcnt;
    __shared__ int      s_segc[SEGS];

    #pragma unroll 4
    for (int i = tid; i < HSIZE; i += NT) {
        h_key[i] = -1;
        h_cnt[i] = 0;
        h_rec[i] = 0u;
    }
    if (tid == 0) s_maxcnt = 0;
    if (tid < SEGS) s_segc[tid] = 0;
    __syncthreads();

    const float l2rw = log2f(*rw_p);

    const int2* lrow = reinterpret_cast<const int2*>(loc_seq + (size_t)b * L_SEQ);
    const int2* mrow = reinterpret_cast<const int2*>(mask    + (size_t)b * L_SEQ);
    const int2 lk = lrow[tid];
    const int2 mk = mrow[tid];

    #pragma unroll
    for (int j = 0; j < 2; j++) {
        const int t   = 2 * tid + j;
        const int key = (j == 0) ? lk.x : lk.y;
        const int m   = (j == 0) ? mk.x : mk.y;
        const float rec = m ? exp2f((float)(L_SEQ - 1 - t) * l2rw) : 0.0f;

        unsigned h = ((unsigned)key * 2654435761u) & (HSIZE - 1);
        for (;;) {
            int cur = h_key[h];
            if (cur == key) break;
            if (cur == -1) {
                int prev = atomicCAS(&h_key[h], -1, key);
                if (prev == -1 || prev == key) break;
            }
            h = (h + 1) & (HSIZE - 1);
        }
        atomicAdd(&h_cnt[h], m);
        atomicMax(&h_rec[h], __float_as_uint(rec));
    }
    __syncthreads();

    // block reduce: max frequency count
    int mf = 0;
    #pragma unroll 4
    for (int i = tid; i < HSIZE; i += NT) mf = max(mf, h_cnt[i]);
    #pragma unroll
    for (int o = 16; o > 0; o >>= 1) mf = max(mf, __shfl_xor_sync(0xFFFFFFFFu, mf, o));
    if ((tid & 31) == 0) atomicMax(&s_maxcnt, mf);
    __syncthreads();

    const float inv = (*fw_p) / fmaxf((float)s_maxcnt, 1.0f);

    // compact final values into per-(row,seg) buckets
    #pragma unroll 4
    for (int i = tid; i < HSIZE; i += NT) {
        const int key = h_key[i];
        if (key >= 0) {
            const float val = __uint_as_float(h_rec[i]) + (float)h_cnt[i] * inv;
            const int seg = key / SEG_LEN;
            const int pos = atomicAdd(&s_segc[seg], 1);
            const int base = (b * SEGS + seg) * CAP;
            g_key[base + pos] = key;
            g_val[base + pos] = val;
        }
    }
    __syncthreads();
    if (tid < SEGS) g_cnt[b * SEGS + tid] = s_segc[tid];
}

// ---------------------------------------------------------------------------
// Secondary (PDL): one CTA per (row, segment). Zero own segment with the
// proven STG-f4 engine (overlaps the primary), then wait on the grid
// dependency (primary long finished) and scatter own bucket. All store
// ordering is CTA-local.
// ---------------------------------------------------------------------------
__global__ __launch_bounds__(NT, 8)
void fill_kernel(float* __restrict__ out)
{
    const int b   = blockIdx.x / SEGS;
    const int seg = blockIdx.x % SEGS;
    const int tid = threadIdx.x;

    const int col0 = seg * SEG_LEN;
    const int col1 = min(col0 + SEG_LEN, N_LOC);

    float*  row  = out + (size_t)b * N_LOC;
    float4* row4 = reinterpret_cast<float4*>(row);
    const float4 z = make_float4(0.f, 0.f, 0.f, 0.f);

    #pragma unroll 2
    for (int i = col0 / 4 + tid; i < col1 / 4; i += NT)
        row4[i] = z;

    __syncthreads();                               // order zero stores in-CTA

    // wait for primary grid (build) results to be visible
    asm volatile("griddepcontrol.wait;" ::: "memory");

    const int slot = b * SEGS + seg;
    const int n    = g_cnt[slot];
    const int base = slot * CAP;

    for (int i = tid; i < n; i += NT)
        row[g_key[base + i]] = g_val[base + i];
}

extern "C" void kernel_launch(void* const* d_in, const int* in_sizes, int n_in,
                              void* d_out, int out_size)
{
    const int*   loc_seq = (const int*)  d_in[0];   // (B, L) int32
    const int*   mask    = (const int*)  d_in[1];   // (B, L) int32
    const float* rw      = (const float*)d_in[2];   // scalar
    const float* fw      = (const float*)d_in[3];   // scalar
    float*       out     = (float*)d_out;           // (B, N) float32

    // Primary
    build_kernel<<<B_SZ, NT>>>(loc_seq, mask, rw, fw);

    // Secondary with Programmatic Dependent Launch: may begin executing while
    // the primary runs; griddepcontrol.wait inside provides the ordering.
    cudaLaunchConfig_t cfg = {};
    cfg.gridDim  = dim3(B_SZ * SEGS);
    cfg.blockDim = dim3(NT);
    cfg.dynamicSmemBytes = 0;
    cfg.stream = 0;   // legacy default stream (the one being captured)
    cudaLaunchAttribute attrs[1];
    attrs[0].id = cudaLaunchAttributeProgrammaticStreamSerialization;
    attrs[0].val.programmaticStreamSerializationAllowed = 1;
    cfg.attrs = attrs;
    cfg.numAttrs = 1;
    cudaLaunchKernelEx(&cfg, fill_kernel, (float*)d_out);
}

// round 15
// speedup vs baseline: 1.1028x; 1.1028x over previous
#include <cuda_runtime.h>
#include <cstdint>

// Fixed shapes per reference: B=256, L=512, N=50000
constexpr int B_SZ   = 256;
constexpr int L_SEQ  = 512;
constexpr int N_LOC  = 50000;
constexpr int HSIZE  = 1024;             // hash slots (pow2), load factor <= 0.5
constexpr int NT     = 256;
constexpr int ZSEGS  = 7;                // zeroer CTAs per row
constexpr int SEG_F  = 7144;             // floats per segment (7*7144=50008>=50000, mult of 4)
constexpr int CAP    = 512;              // max distinct keys per (row,seg)
constexpr int PAD    = 32;               // 128B padding between row flags
constexpr int N_ZERO = B_SZ * ZSEGS;     // 1792
constexpr int GRID   = B_SZ + N_ZERO;    // 2048

// Global scratch (__device__ arrays only)
__device__ int   g_flag[B_SZ * PAD];     // 0 at load; builder +7, each zeroer -1 -> 0
__device__ int   g_cnt[B_SZ * ZSEGS];
__device__ int   g_key[B_SZ * ZSEGS * CAP];
__device__ float g_val[B_SZ * ZSEGS * CAP];

__global__ __launch_bounds__(NT, 8)
void fused_kernel(const int* __restrict__ loc_seq,
                  const int* __restrict__ mask,
                  const float* __restrict__ rw_p,
                  const float* __restrict__ fw_p,
                  float* __restrict__ out)
{
    const int bid = blockIdx.x;
    const int tid = threadIdx.x;

    if (bid < B_SZ) {
        // ================= builder (wave-1 resident, done in ~3 us) =================
        const int b = bid;

        __shared__ int      h_key[HSIZE];
        __shared__ int      h_cnt[HSIZE];
        __shared__ unsigned h_rec[HSIZE];   // float bits; all values >= 0
        __shared__ int      s_maxcnt;
        __shared__ int      s_segc[ZSEGS];

        #pragma unroll 4
        for (int i = tid; i < HSIZE; i += NT) {
            h_key[i] = -1;
            h_cnt[i] = 0;
            h_rec[i] = 0u;
        }
        if (tid == 0) s_maxcnt = 0;
        if (tid < ZSEGS) s_segc[tid] = 0;
        __syncthreads();

        const float l2rw = log2f(*rw_p);

        const int2* lrow = reinterpret_cast<const int2*>(loc_seq + (size_t)b * L_SEQ);
        const int2* mrow = reinterpret_cast<const int2*>(mask    + (size_t)b * L_SEQ);
        const int2 lk = lrow[tid];
        const int2 mk = mrow[tid];

        #pragma unroll
        for (int j = 0; j < 2; j++) {
            const int t   = 2 * tid + j;
            const int key = (j == 0) ? lk.x : lk.y;
            const int m   = (j == 0) ? mk.x : mk.y;
            const float rec = m ? exp2f((float)(L_SEQ - 1 - t) * l2rw) : 0.0f;

            unsigned h = ((unsigned)key * 2654435761u) & (HSIZE - 1);
            for (;;) {
                int cur = h_key[h];
                if (cur == key) break;
                if (cur == -1) {
                    int prev = atomicCAS(&h_key[h], -1, key);
                    if (prev == -1 || prev == key) break;
                }
                h = (h + 1) & (HSIZE - 1);
            }
            atomicAdd(&h_cnt[h], m);
            atomicMax(&h_rec[h], __float_as_uint(rec));
        }
        __syncthreads();

        int mf = 0;
        #pragma unroll 4
        for (int i = tid; i < HSIZE; i += NT) mf = max(mf, h_cnt[i]);
        #pragma unroll
        for (int o = 16; o > 0; o >>= 1) mf = max(mf, __shfl_xor_sync(0xFFFFFFFFu, mf, o));
        if ((tid & 31) == 0) atomicMax(&s_maxcnt, mf);
        __syncthreads();

        const float inv = (*fw_p) / fmaxf((float)s_maxcnt, 1.0f);

        // compact final values into per-(row,seg) buckets
        #pragma unroll 4
        for (int i = tid; i < HSIZE; i += NT) {
            const int key = h_key[i];
            if (key >= 0) {
                const float val = __uint_as_float(h_rec[i]) + (float)h_cnt[i] * inv;
                const int seg = key / SEG_F;
                const int pos = atomicAdd(&s_segc[seg], 1);
                const int base = (b * ZSEGS + seg) * CAP;
                g_key[base + pos] = key;
                g_val[base + pos] = val;
            }
        }
        __syncthreads();
        if (tid < ZSEGS) g_cnt[b * ZSEGS + tid] = s_segc[tid];
        __syncthreads();   // all bucket stores happen-before tid0's release below

        if (tid == 0) {
            int* flagp = &g_flag[b * PAD];
            asm volatile("red.release.gpu.global.add.s32 [%0], %1;"
                         :: "l"(flagp), "r"(ZSEGS) : "memory");
        }
        return;
    }

    // ================= zeroer (the 11-us store engine + own-segment scatter) ========
    const int zi  = bid - B_SZ;              // 0..1791
    const int b   = zi / ZSEGS;
    const int seg = zi % ZSEGS;

    float* const row = out + (size_t)b * N_LOC;
    const int e0 = seg * SEG_F;
    const int e1 = min(e0 + SEG_F, N_LOC);

    {
        float4* row4 = reinterpret_cast<float4*>(row);
        const float4 z = make_float4(0.f, 0.f, 0.f, 0.f);
        #pragma unroll 4
        for (int i = e0 / 4 + tid; i < e1 / 4; i += NT)
            row4[i] = z;
    }
    __syncthreads();                         // order zero stores before scatter (cta scope)

    // acquire the builder's bucket; builder finished ~8 us ago -> spin ~never iterates
    if (tid == 0) {
        int* flagp = &g_flag[b * PAD];
        int v;
        for (;;) {
            asm volatile("ld.acquire.gpu.global.s32 %0, [%1];"
                         : "=r"(v) : "l"(flagp) : "memory");
            if (v > 0) break;
            __nanosleep(32);
        }
        asm volatile("red.relaxed.gpu.global.add.s32 [%0], %1;"
                     :: "l"(flagp), "r"(-1) : "memory");   // replay-safe: ends at 0
    }
    __syncthreads();

    const int slot = b * ZSEGS + seg;
    const int n    = g_cnt[slot];
    const int base = slot * CAP;
    for (int i = tid; i < n; i += NT)
        row[g_key[base + i]] = g_val[base + i];
}

extern "C" void kernel_launch(void* const* d_in, const int* in_sizes, int n_in,
                              void* d_out, int out_size)
{
    const int*   loc_seq = (const int*)  d_in[0];   // (B, L) int32
    const int*   mask    = (const int*)  d_in[1];   // (B, L) int32
    const float* rw      = (const float*)d_in[2];   // scalar
    const float* fw      = (const float*)d_in[3];   // scalar
    float*       out     = (float*)d_out;           // (B, N) float32

    fused_kernel<<<GRID, NT>>>(loc_seq, mask, rw, fw, out);
}